// round 1
// baseline (speedup 1.0000x reference)
#include <cuda_runtime.h>
#include <cstddef>
#include <cstdint>

// ---------------------------------------------------------------------------
// Problem constants
// ---------------------------------------------------------------------------
#define NC 100000
#define NM 50000
#define ND 10000

// Scratch layout (floats):
//   cntR : 320000                  (per-relation reciprocal in-degree)
//   P    : 6,400,000               (projected source features, reused per relation)
//   AGG  : 20,480,000              (per-relation aggregation targets)
//   H    : 10,240,000              (layer-1 hidden states h_c,h_m,h_d)
#define SCRATCH_FLOATS (320000ull + 6400000ull + 20480000ull + 10240000ull)
__device__ float g_scratch[SCRATCH_FLOATS];

// ---------------------------------------------------------------------------
// Small utility kernels
// ---------------------------------------------------------------------------
__global__ void zero4_kernel(float4* __restrict__ p, int n4) {
    int i = blockIdx.x * blockDim.x + threadIdx.x;
    if (i < n4) p[i] = make_float4(0.f, 0.f, 0.f, 0.f);
}

__global__ void count_kernel(const int* __restrict__ dst, int E, float* __restrict__ cnt) {
    int i = blockIdx.x * blockDim.x + threadIdx.x;
    if (i < E) atomicAdd(&cnt[dst[i]], 1.0f);
}

__global__ void recip_kernel(float* __restrict__ p, int n) {
    int i = blockIdx.x * blockDim.x + threadIdx.x;
    if (i < n) p[i] = 1.0f / fmaxf(p[i], 1.0f);
}

// ---------------------------------------------------------------------------
// Edge scatter: AGG[dst] += P[src], 64 floats per edge, vector reductions.
// 16 threads per edge, each handles one float4 column chunk.
// ---------------------------------------------------------------------------
__global__ void scatter_kernel(const float4* __restrict__ P,
                               const int* __restrict__ src,
                               const int* __restrict__ dst,
                               float4* __restrict__ agg, int E) {
    int idx = blockIdx.x * blockDim.x + threadIdx.x;
    int e = idx >> 4;
    if (e >= E) return;
    int c = idx & 15;
    float4 v = P[(size_t)src[e] * 16 + c];
    float4* ptr = agg + (size_t)dst[e] * 16 + c;
    asm volatile("red.global.add.v4.f32 [%0], {%1, %2, %3, %4};"
                 :: "l"(ptr), "f"(v.x), "f"(v.y), "f"(v.z), "f"(v.w)
                 : "memory");
}

// ---------------------------------------------------------------------------
// GEMM: Y[M,64] = X[M,K] @ W[K,64], with fused epilogues.
//   mode 0: Y = X @ W0                                   (projection)
//   mode 1: Y = relu(0.5*(X@(W0+W1) + aggA*rA + aggB*rB + b0 + b1))  (layer-1 combine)
//   mode 2: same as 1 without relu                       (layer-2 combine)
//   mode 3: Y += X @ W0 + b0                             (residual add)
// Block: 64 rows x 64 cols, 256 threads, 4x4 micro-tile per thread.
// ---------------------------------------------------------------------------
template<int K>
__global__ __launch_bounds__(256)
void gemm64_kernel(const float* __restrict__ X,
                   const float* __restrict__ W0, const float* __restrict__ W1,
                   const float* __restrict__ b0, const float* __restrict__ b1,
                   const float* __restrict__ aggA, const float* __restrict__ rA,
                   const float* __restrict__ aggB, const float* __restrict__ rB,
                   float* __restrict__ Y, int M, int mode) {
    constexpr int KB = K / 64;
    __shared__ float Xs[64][65];   // transposed: Xs[k][row], stride 65 -> conflict-free reads
    __shared__ float Ws[64][64];   // Ws[k][col]

    const int t = threadIdx.x;
    const int m0 = blockIdx.x * 64;
    const int k4 = t & 15;   // 0..15
    const int rr = t >> 4;   // 0..15

    float acc[4][4] = {};

    for (int kb = 0; kb < KB; kb++) {
        // Load X tile (64 rows x 64 k) transposed into Xs
        #pragma unroll
        for (int it = 0; it < 4; it++) {
            int row = rr + it * 16;
            int m = m0 + row;
            float4 v = make_float4(0.f, 0.f, 0.f, 0.f);
            if (m < M) v = *(const float4*)(X + (size_t)m * K + kb * 64 + k4 * 4);
            Xs[k4 * 4 + 0][row] = v.x;
            Xs[k4 * 4 + 1][row] = v.y;
            Xs[k4 * 4 + 2][row] = v.z;
            Xs[k4 * 4 + 3][row] = v.w;
        }
        // Load W tile (optionally W0+W1 fused)
        #pragma unroll
        for (int it = 0; it < 4; it++) {
            int k = rr + it * 16;
            float4 w = *(const float4*)(W0 + (size_t)(kb * 64 + k) * 64 + k4 * 4);
            if (W1) {
                float4 w2 = *(const float4*)(W1 + (size_t)(kb * 64 + k) * 64 + k4 * 4);
                w.x += w2.x; w.y += w2.y; w.z += w2.z; w.w += w2.w;
            }
            *(float4*)(&Ws[k][k4 * 4]) = w;
        }
        __syncthreads();

        const int r0 = rr * 4;
        const int c0 = k4 * 4;
        #pragma unroll 16
        for (int k = 0; k < 64; k++) {
            float a0 = Xs[k][r0 + 0];
            float a1 = Xs[k][r0 + 1];
            float a2 = Xs[k][r0 + 2];
            float a3 = Xs[k][r0 + 3];
            float4 b = *(const float4*)(&Ws[k][c0]);
            acc[0][0] = fmaf(a0, b.x, acc[0][0]);
            acc[0][1] = fmaf(a0, b.y, acc[0][1]);
            acc[0][2] = fmaf(a0, b.z, acc[0][2]);
            acc[0][3] = fmaf(a0, b.w, acc[0][3]);
            acc[1][0] = fmaf(a1, b.x, acc[1][0]);
            acc[1][1] = fmaf(a1, b.y, acc[1][1]);
            acc[1][2] = fmaf(a1, b.z, acc[1][2]);
            acc[1][3] = fmaf(a1, b.w, acc[1][3]);
            acc[2][0] = fmaf(a2, b.x, acc[2][0]);
            acc[2][1] = fmaf(a2, b.y, acc[2][1]);
            acc[2][2] = fmaf(a2, b.z, acc[2][2]);
            acc[2][3] = fmaf(a2, b.w, acc[2][3]);
            acc[3][0] = fmaf(a3, b.x, acc[3][0]);
            acc[3][1] = fmaf(a3, b.y, acc[3][1]);
            acc[3][2] = fmaf(a3, b.z, acc[3][2]);
            acc[3][3] = fmaf(a3, b.w, acc[3][3]);
        }
        __syncthreads();
    }

    // Epilogue
    const int r0 = rr * 4;
    const int c0 = k4 * 4;
    #pragma unroll
    for (int i = 0; i < 4; i++) {
        int m = m0 + r0 + i;
        if (m >= M) break;
        size_t base = (size_t)m * 64;
        #pragma unroll
        for (int j = 0; j < 4; j++) {
            int c = c0 + j;
            float v = acc[i][j];
            if (mode == 0) {
                Y[base + c] = v;
            } else if (mode == 3) {
                Y[base + c] += v + b0[c];
            } else {
                v = 0.5f * (v + aggA[base + c] * rA[m] + aggB[base + c] * rB[m]
                            + b0[c] + b1[c]);
                if (mode == 1) v = fmaxf(v, 0.0f);
                Y[base + c] = v;
            }
        }
    }
}

// ---------------------------------------------------------------------------
// Row-wise L2 normalization: one warp per 64-wide row.
// ---------------------------------------------------------------------------
__global__ void l2norm_kernel(float* __restrict__ Y, int rows) {
    int gw = (blockIdx.x * blockDim.x + threadIdx.x) >> 5;
    int lane = threadIdx.x & 31;
    if (gw >= rows) return;
    size_t base = (size_t)gw * 64;
    float a = Y[base + lane];
    float b = Y[base + 32 + lane];
    float s = a * a + b * b;
    #pragma unroll
    for (int off = 16; off > 0; off >>= 1)
        s += __shfl_xor_sync(0xffffffffu, s, off);
    float inv = 1.0f / fmaxf(sqrtf(s), 1e-12f);
    Y[base + lane] = a * inv;
    Y[base + 32 + lane] = b * inv;
}

// ---------------------------------------------------------------------------
// Host orchestration
// ---------------------------------------------------------------------------
extern "C" void kernel_launch(void* const* d_in, const int* in_sizes, int n_in,
                              void* d_out, int out_size) {
    const float* xc  = (const float*)d_in[0];
    const float* xm  = (const float*)d_in[1];
    const float* xd  = (const float*)d_in[2];
    // relation order: 0=c->m, 1=m->d, 2=c->d, 3=m->c, 4=d->m, 5=d->c
    const int srcIdx[6] = {3, 5, 7, 9, 11, 13};
    const int dstIdx[6] = {4, 6, 8, 10, 12, 14};
    const int* SRC[6]; const int* DST[6]; int EE[6];
    for (int r = 0; r < 6; r++) {
        SRC[r] = (const int*)d_in[srcIdx[r]];
        DST[r] = (const int*)d_in[dstIdx[r]];
        EE[r]  = in_sizes[srcIdx[r]];
    }
    const float* W1l  = (const float*)d_in[15];
    const float* W1r  = (const float*)d_in[16];
    const float* b1   = (const float*)d_in[17];
    const float* W2l  = (const float*)d_in[18];
    const float* W2r  = (const float*)d_in[19];
    const float* b2   = (const float*)d_in[20];
    const float* Wres = (const float*)d_in[21];
    const float* bres = (const float*)d_in[22];
    float* out = (float*)d_out;

    const int NSRC[6]    = {NC, NM, NC, NM, ND, ND};
    const int NDSTA[6]   = {NM, ND, ND, NC, NM, NC};
    const int srcType[6] = {0, 1, 0, 1, 2, 2};  // 0=c,1=m,2=d

    float* S = nullptr;
    cudaGetSymbolAddress((void**)&S, g_scratch);

    float* cntR = S;
    float* P    = S + 320000;
    float* AGG  = P + 6400000;
    float* H    = AGG + 20480000;

    size_t cOff[6], aOff[6];
    { size_t c = 0, a = 0;
      for (int r = 0; r < 6; r++) { cOff[r] = c; aOff[r] = a;
                                    c += NDSTA[r]; a += (size_t)NDSTA[r] * 64; } }

    float* Hc = H;
    float* Hm = Hc + (size_t)NC * 64;
    float* Hd = Hm + (size_t)NM * 64;
    const float* X1[3] = {xc, xm, xd};
    const float* HX[3] = {Hc, Hm, Hd};

    float* Oc = out;
    float* Om = Oc + (size_t)NC * 64;
    float* Od = Om + (size_t)NM * 64;

    // ---- per-relation in-degree reciprocals (shared by both layers) ----
    zero4_kernel<<<(320000 / 4 + 255) / 256, 256>>>((float4*)cntR, 320000 / 4);
    for (int r = 0; r < 6; r++)
        count_kernel<<<(EE[r] + 255) / 256, 256>>>(DST[r], EE[r], cntR + cOff[r]);
    recip_kernel<<<(320000 + 255) / 256, 256>>>(cntR, 320000);

    // ---- layer 1 (F=128 -> 64) ----
    zero4_kernel<<<(20480000 / 4 + 255) / 256, 256>>>((float4*)AGG, 20480000 / 4);
    for (int r = 0; r < 6; r++) {
        int M = NSRC[r];
        gemm64_kernel<128><<<(M + 63) / 64, 256>>>(
            X1[srcType[r]], W1l + (size_t)r * 8192, nullptr,
            nullptr, nullptr, nullptr, nullptr, nullptr, nullptr, P, M, 0);
        scatter_kernel<<<(EE[r] * 16 + 255) / 256, 256>>>(
            (const float4*)P, SRC[r], DST[r], (float4*)(AGG + aOff[r]), EE[r]);
    }
    // combines: m <- (0,4), d <- (1,2), c <- (3,5)
    gemm64_kernel<128><<<(NM + 63) / 64, 256>>>(
        xm, W1r + 0 * 8192, W1r + 4 * 8192, b1 + 0 * 64, b1 + 4 * 64,
        AGG + aOff[0], cntR + cOff[0], AGG + aOff[4], cntR + cOff[4], Hm, NM, 1);
    gemm64_kernel<128><<<(ND + 63) / 64, 256>>>(
        xd, W1r + 1 * 8192, W1r + 2 * 8192, b1 + 1 * 64, b1 + 2 * 64,
        AGG + aOff[1], cntR + cOff[1], AGG + aOff[2], cntR + cOff[2], Hd, ND, 1);
    gemm64_kernel<128><<<(NC + 63) / 64, 256>>>(
        xc, W1r + 3 * 8192, W1r + 5 * 8192, b1 + 3 * 64, b1 + 5 * 64,
        AGG + aOff[3], cntR + cOff[3], AGG + aOff[5], cntR + cOff[5], Hc, NC, 1);

    // ---- layer 2 (F=64 -> 64) ----
    zero4_kernel<<<(20480000 / 4 + 255) / 256, 256>>>((float4*)AGG, 20480000 / 4);
    for (int r = 0; r < 6; r++) {
        int M = NSRC[r];
        gemm64_kernel<64><<<(M + 63) / 64, 256>>>(
            HX[srcType[r]], W2l + (size_t)r * 4096, nullptr,
            nullptr, nullptr, nullptr, nullptr, nullptr, nullptr, P, M, 0);
        scatter_kernel<<<(EE[r] * 16 + 255) / 256, 256>>>(
            (const float4*)P, SRC[r], DST[r], (float4*)(AGG + aOff[r]), EE[r]);
    }
    gemm64_kernel<64><<<(NM + 63) / 64, 256>>>(
        Hm, W2r + 0 * 4096, W2r + 4 * 4096, b2 + 0 * 64, b2 + 4 * 64,
        AGG + aOff[0], cntR + cOff[0], AGG + aOff[4], cntR + cOff[4], Om, NM, 2);
    gemm64_kernel<64><<<(ND + 63) / 64, 256>>>(
        Hd, W2r + 1 * 4096, W2r + 2 * 4096, b2 + 1 * 64, b2 + 2 * 64,
        AGG + aOff[1], cntR + cOff[1], AGG + aOff[2], cntR + cOff[2], Od, ND, 2);
    gemm64_kernel<64><<<(NC + 63) / 64, 256>>>(
        Hc, W2r + 3 * 4096, W2r + 5 * 4096, b2 + 3 * 64, b2 + 5 * 64,
        AGG + aOff[3], cntR + cOff[3], AGG + aOff[5], cntR + cOff[5], Oc, NC, 2);

    // ---- residual projections (K=128) ----
    gemm64_kernel<128><<<(NC + 63) / 64, 256>>>(
        xc, Wres + 0 * 8192, nullptr, bres + 0 * 64, nullptr,
        nullptr, nullptr, nullptr, nullptr, Oc, NC, 3);
    gemm64_kernel<128><<<(NM + 63) / 64, 256>>>(
        xm, Wres + 1 * 8192, nullptr, bres + 1 * 64, nullptr,
        nullptr, nullptr, nullptr, nullptr, Om, NM, 3);
    gemm64_kernel<128><<<(ND + 63) / 64, 256>>>(
        xd, Wres + 2 * 8192, nullptr, bres + 2 * 64, nullptr,
        nullptr, nullptr, nullptr, nullptr, Od, ND, 3);

    // ---- row-wise L2 norm over the whole output ----
    const int rows = NC + NM + ND;
    l2norm_kernel<<<(rows * 32 + 255) / 256, 256>>>(out, rows);
}